// round 16
// baseline (speedup 1.0000x reference)
#include <cuda_runtime.h>
#include <cuda_fp16.h>
#include <cstdint>

#define T_TOK 8192
#define HDIM  2048
#define NEXP  8

// GEMM tile config (fp16 mma.sync; B via cp.async.bulk from pre-swizzled gmem)
#define BM 128
#define BN 256
#define BKC 64
#define NCHUNK (HDIM / BKC)        // 32
#define NSTAGE 4
#define A_OFF 0                    // 16 KB (128 rows x 128B)
#define B_OFF 16384                // 32 KB (256 rows x 128B)
#define STAGE_BYTES 49152
#define SM_HDR 1024
#define SMEM_TOTAL (SM_HDR + NSTAGE * STAGE_BYTES)   // 197632
#define B_BLOCK_BYTES 32768

// merged prep block partition (convert-x fused into router blocks)
#define NB_ROUTE 1024
#define NB_TRANS 8192
#define NB_INIT  1024
#define NB_PREP  (NB_ROUTE + NB_TRANS + NB_INIT)

// ---------------- device scratch (no allocations allowed) -------------------
__device__ int    d_cnt[NEXP];     // live counters (always return to 0 per launch)
__device__ int    d_cnt2[NEXP];    // snapshot read by the GEMM
__device__ int    d_ticket;        // router-block completion ticket
__device__ int    d_list[NEXP * T_TOK];
__device__ float  d_gatev[NEXP * T_TOK];
__device__ __half d_xh[(size_t)T_TOK * HDIM];
// We^T pre-swizzled tile layout: block[(e*8+nt)*32+c] of 32KB; inside:
// swz128(row*128 + (kk>>3)*16) + (kk&7)*2  for n=nt*256+row, k=c*64+kk
__device__ __half d_wtile[(size_t)NEXP * HDIM * HDIM];

// ---------------- helpers ---------------------------------------------------
__device__ __forceinline__ uint32_t smem_u32(const void* p) {
    uint32_t a;
    asm("{ .reg .u64 t; cvta.to.shared.u64 t, %1; cvt.u32.u64 %0, t; }" : "=r"(a) : "l"(p));
    return a;
}
__device__ __forceinline__ uint32_t swz128(uint32_t o) { return o ^ ((o >> 3) & 0x70); }
__device__ __forceinline__ void cp16(uint32_t dst, const void* src) {
    asm volatile("cp.async.cg.shared.global [%0], [%1], 16;" :: "r"(dst), "l"(src));
}
__device__ __forceinline__ void ldm4(uint32_t addr, uint32_t& r0, uint32_t& r1,
                                     uint32_t& r2, uint32_t& r3) {
    asm volatile("ldmatrix.sync.aligned.m8n8.x4.shared.b16 {%0,%1,%2,%3}, [%4];"
                 : "=r"(r0), "=r"(r1), "=r"(r2), "=r"(r3) : "r"(addr));
}
__device__ __forceinline__ void mma16816(float* c, const uint32_t* a,
                                         uint32_t b0, uint32_t b1) {
    asm volatile(
        "mma.sync.aligned.m16n8k16.row.col.f32.f16.f16.f32 "
        "{%0,%1,%2,%3}, {%4,%5,%6,%7}, {%8,%9}, {%0,%1,%2,%3};"
        : "+f"(c[0]), "+f"(c[1]), "+f"(c[2]), "+f"(c[3])
        : "r"(a[0]), "r"(a[1]), "r"(a[2]), "r"(a[3]), "r"(b0), "r"(b1));
}
__device__ __forceinline__ void redv2(float* addr, float a, float b) {
    asm volatile("red.global.add.v2.f32 [%0], {%1, %2};"
                 :: "l"(addr), "f"(a), "f"(b) : "memory");
}
__device__ __forceinline__ void mbar_init(uint32_t a, uint32_t cnt) {
    asm volatile("mbarrier.init.shared.b64 [%0], %1;" :: "r"(a), "r"(cnt) : "memory");
}
__device__ __forceinline__ void mbar_expect_tx(uint32_t a, uint32_t tx) {
    asm volatile("mbarrier.arrive.expect_tx.shared.b64 _, [%0], %1;"
                 :: "r"(a), "r"(tx) : "memory");
}
__device__ __forceinline__ void mbar_wait(uint32_t a, uint32_t ph) {
    asm volatile(
        "{\n\t.reg .pred P;\n\tWL_%=:\n\t"
        "mbarrier.try_wait.parity.acquire.cta.shared::cta.b64 P, [%0], %1, 0x989680;\n\t"
        "@P bra.uni WD_%=;\n\tbra.uni WL_%=;\n\tWD_%=:\n\t}"
        :: "r"(a), "r"(ph) : "memory");
}
__device__ __forceinline__ void bulk_ld(uint32_t dst, const void* src,
                                        uint32_t bytes, uint32_t mbar) {
    asm volatile("cp.async.bulk.shared::cta.global.mbarrier::complete_tx::bytes "
                 "[%0], [%1], %2, [%3];"
                 :: "r"(dst), "l"(src), "r"(bytes), "r"(mbar) : "memory");
}

// ---------------- kernel A: merged prep --------------------------------------
// blocks [0, NB_ROUTE)              : router + x->fp16 convert (warp per token)
// blocks [NB_ROUTE, +NB_TRANS)      : transpose+convert We tiles
// blocks [NB_ROUTE+NB_TRANS, +NB_INIT): zero out
// Counter lifecycle: d_cnt starts at 0 (module load / previous-launch reset).
// Router blocks atomically build lists; the LAST router block (ticket) copies
// counts into d_cnt2 (read by GEMM) and resets d_cnt + ticket to 0, so every
// launch performs identical work on identical state.
__global__ void __launch_bounds__(256)
prep_kernel(const float* __restrict__ x, const float* __restrict__ Wg,
            const float* __restrict__ bg, const float* __restrict__ We,
            float* __restrict__ out) {
    __shared__ float tile[64][68];
    const int b = blockIdx.x;
    const int tid = threadIdx.x;

    if (b < NB_ROUTE) {
        // ---------------- router + convert (warp per token) ----------------
        const int lane = tid & 31;
        const int t = b * 8 + (tid >> 5);
        float acc[NEXP];
#pragma unroll
        for (int e = 0; e < NEXP; e++) acc[e] = 0.f;
        const float* xr = x + (size_t)t * HDIM;
#pragma unroll 4
        for (int j = 0; j < HDIM / 32; j++) {
            const int h = lane + 32 * j;
            const float xs = xr[h];
            const float4* wr = (const float4*)(Wg + (size_t)h * NEXP);
            float4 w0 = wr[0], w1 = wr[1];
            acc[0] += xs * w0.x; acc[1] += xs * w0.y; acc[2] += xs * w0.z; acc[3] += xs * w0.w;
            acc[4] += xs * w1.x; acc[5] += xs * w1.y; acc[6] += xs * w1.z; acc[7] += xs * w1.w;
        }
        // convert loop: re-read row (L1 hits), write fp16 — overlaps reduction
        {
            const float4* xr4 = (const float4*)xr;
            __half2* xh = (__half2*)(d_xh + (size_t)t * HDIM);
#pragma unroll 4
            for (int j = 0; j < 16; j++) {
                const int i4 = lane + 32 * j;
                float4 v = xr4[i4];
                xh[2 * i4]     = __floats2half2_rn(v.x, v.y);
                xh[2 * i4 + 1] = __floats2half2_rn(v.z, v.w);
            }
        }
#pragma unroll
        for (int e = 0; e < NEXP; e++) {
#pragma unroll
            for (int s = 16; s > 0; s >>= 1)
                acc[e] += __shfl_xor_sync(0xFFFFFFFFu, acc[e], s);
        }
        if (lane == 0) {
#pragma unroll
            for (int e = 0; e < NEXP; e++) acc[e] += bg[e];
            float m = acc[0];
#pragma unroll
            for (int e = 1; e < NEXP; e++) m = fmaxf(m, acc[e]);
            float p[NEXP], s = 0.f;
#pragma unroll
            for (int e = 0; e < NEXP; e++) { p[e] = __expf(acc[e] - m); s += p[e]; }
            float inv = 1.f / s;
#pragma unroll
            for (int e = 0; e < NEXP; e++) p[e] *= inv;
            int i0 = 0;
#pragma unroll
            for (int e = 1; e < NEXP; e++) if (p[e] > p[i0]) i0 = e;
            int i1 = (i0 == 0) ? 1 : 0;
#pragma unroll
            for (int e = 0; e < NEXP; e++) if (e != i0 && p[e] > p[i1]) i1 = e;
            int pos0 = atomicAdd(&d_cnt[i0], 1);
            d_list[i0 * T_TOK + pos0] = t;  d_gatev[i0 * T_TOK + pos0] = p[i0];
            int pos1 = atomicAdd(&d_cnt[i1], 1);
            d_list[i1 * T_TOK + pos1] = t;  d_gatev[i1 * T_TOK + pos1] = p[i1];
        }
        // ---- ticket: last router block snapshots counters and resets state ----
        __syncthreads();
        if (tid == 0) {
            __threadfence();
            int old = atomicAdd(&d_ticket, 1);
            if (old == NB_ROUTE - 1) {
#pragma unroll
                for (int e = 0; e < NEXP; e++) { d_cnt2[e] = d_cnt[e]; d_cnt[e] = 0; }
                d_ticket = 0;
                __threadfence();
            }
        }
    } else if (b < NB_ROUTE + NB_TRANS) {
        // ---------------- transpose+convert We (64n x 64k tile) ----------------
        const int bt = b - NB_ROUTE;
        const int e  = bt >> 10;               // / 1024
        const int rem = bt & 1023;
        const int n0 = (rem & 31) * 64;
        const int k0 = (rem >> 5) * 64;

        const float* src = We + ((size_t)e * HDIM + k0) * HDIM + n0;
#pragma unroll
        for (int i = 0; i < 4; i++) {
            const int idx = tid + 256 * i;
            const int r  = idx >> 4;
            const int c4 = idx & 15;
            float4 v = *(const float4*)(src + (size_t)r * HDIM + c4 * 4);
            tile[r][c4 * 4 + 0] = v.x; tile[r][c4 * 4 + 1] = v.y;
            tile[r][c4 * 4 + 2] = v.z; tile[r][c4 * 4 + 3] = v.w;
        }
        __syncthreads();

        const int nl = tid >> 2;
        const int n  = n0 + nl;
        const int nt = n >> 8;
        const int row = n & 255;
        const int c  = k0 >> 6;
        char* blk = (char*)d_wtile + (((size_t)(e * 8 + nt) * 32 + c) * B_BLOCK_BYTES);
#pragma unroll
        for (int gi = 0; gi < 2; gi++) {
            const int g  = (tid & 3) + gi * 4;
            const int kk = g * 8;
            __half h[8];
#pragma unroll
            for (int j = 0; j < 8; j++) h[j] = __float2half_rn(tile[kk + j][nl]);
            const uint32_t off = swz128((uint32_t)(row * 128 + g * 16));
            *(uint4*)(blk + off) = *(const uint4*)h;
        }
    } else {
        // ---------------- zero output ----------------
        const int bi = b - NB_ROUTE - NB_TRANS;
        const int n4 = (T_TOK * HDIM) / 4;
        float4 z = make_float4(0.f, 0.f, 0.f, 0.f);
        float4* o4 = (float4*)out;
        for (int j = bi * 256 + tid; j < n4; j += NB_INIT * 256) o4[j] = z;
    }
}

// ---------------- kernel B: grouped GEMM, A via cp.async, B via bulk ---------
__global__ void __launch_bounds__(256, 1)
moe_gemm_mma(const float* __restrict__ be, float* __restrict__ out) {
    const int e = blockIdx.z;
    const int cnt = d_cnt2[e];
    const int m0 = blockIdx.y * BM;
    if (m0 >= cnt) return;
    const int nt = blockIdx.x;
    const int n0 = nt * BN;

    extern __shared__ char smem[];
    const uint32_t sb = smem_u32(smem);
    const int tid  = threadIdx.x;
    const int wid  = tid >> 5;
    const int lane = tid & 31;
    const int wm   = wid >> 2;
    const int wn   = wid & 3;

    int*   sTok  = (int*)smem;
    float* sGate = (float*)(smem + 512);
    const uint32_t mbar0 = sb + 960;     // 4 mbarriers: 960..992

    if (tid == 0) {
#pragma unroll
        for (int s = 0; s < NSTAGE; s++) mbar_init(mbar0 + 8 * s, 1);
    }
    if (tid < BM) {
        int r = m0 + tid;
        if (r < cnt) { sTok[tid] = d_list[e * T_TOK + r]; sGate[tid] = d_gatev[e * T_TOK + r]; }
        else         { sTok[tid] = 0;                      sGate[tid] = 0.f; }
    }
    asm volatile("fence.proxy.async.shared::cta;" ::: "memory");
    __syncthreads();

    const int row2 = tid >> 1;
    const int half = tid & 1;
    uint32_t sD[4];
#pragma unroll
    for (int i = 0; i < 4; i++) {
        uint32_t o = row2 * 128 + (half * 4 + i) * 16;
        sD[i] = swz128(o);
    }
    const __half* aS = d_xh + (size_t)sTok[row2] * HDIM + half * 32;
    const char* bBase = (const char*)d_wtile + ((size_t)(e * 8 + nt) * 32) * B_BLOCK_BYTES;

    const uint32_t stgBase = sb + SM_HDR;

#define ISSUE_CHUNK(sidx_, c_)                                                \
    {                                                                         \
        const uint32_t stg_ = stgBase + (sidx_) * STAGE_BYTES;                \
        if (tid == 0) {                                                       \
            mbar_expect_tx(mbar0 + 8 * (sidx_), B_BLOCK_BYTES);               \
            bulk_ld(stg_ + B_OFF, bBase + (size_t)(c_) * B_BLOCK_BYTES,       \
                    B_BLOCK_BYTES, mbar0 + 8 * (sidx_));                      \
        }                                                                     \
        _Pragma("unroll")                                                     \
        for (int i = 0; i < 4; i++)                                           \
            cp16(stg_ + A_OFF + sD[i], aS + (c_) * BKC + i * 8);              \
        asm volatile("cp.async.commit_group;" ::: "memory");                  \
    }

    uint32_t aRow[4], bRow[4];
#pragma unroll
    for (int mi = 0; mi < 4; mi++) aRow[mi] = wm * 64 + mi * 16 + (lane & 15);
#pragma unroll
    for (int j = 0; j < 4; j++)    bRow[j]  = wn * 64 + j * 16 + (lane & 15);
    const uint32_t kcHalf = (lane >> 4);

    float acc[4][8][4];
#pragma unroll
    for (int mi = 0; mi < 4; mi++)
#pragma unroll
        for (int nj = 0; nj < 8; nj++)
#pragma unroll
            for (int q = 0; q < 4; q++) acc[mi][nj][q] = 0.f;

    ISSUE_CHUNK(0, 0);
    ISSUE_CHUNK(1, 1);
    ISSUE_CHUNK(2, 2);
    ISSUE_CHUNK(3, 3);

    int sidx = 0;
    for (int c = 0; c < NCHUNK; c++) {
        asm volatile("cp.async.wait_group 3;" ::: "memory");
        mbar_wait(mbar0 + 8 * sidx, (c / NSTAGE) & 1);
        __syncthreads();
        const uint32_t stage = stgBase + sidx * STAGE_BYTES;

#pragma unroll
        for (int ks = 0; ks < 4; ks++) {
            const uint32_t kc = ks * 2 + kcHalf;
            uint32_t a[4][4];
#pragma unroll
            for (int mi = 0; mi < 4; mi++) {
                uint32_t off = aRow[mi] * 128 + ((kc ^ (aRow[mi] & 7)) << 4);
                ldm4(stage + A_OFF + off, a[mi][0], a[mi][1], a[mi][2], a[mi][3]);
            }
            uint32_t bfr[4][4];
#pragma unroll
            for (int j = 0; j < 4; j++) {
                uint32_t off = bRow[j] * 128 + ((kc ^ (bRow[j] & 7)) << 4);
                ldm4(stage + B_OFF + off, bfr[j][0], bfr[j][1], bfr[j][2], bfr[j][3]);
            }
#pragma unroll
            for (int mi = 0; mi < 4; mi++) {
#pragma unroll
                for (int nj = 0; nj < 8; nj++) {
                    const int j = nj >> 1, h = nj & 1;
                    mma16816(acc[mi][nj], a[mi], bfr[j][h], bfr[j][h + 2]);
                }
            }
        }

        __syncthreads();
        if (c + NSTAGE < NCHUNK) {
            ISSUE_CHUNK(sidx, c + NSTAGE);
        } else {
            asm volatile("cp.async.commit_group;" ::: "memory");
        }
        sidx = (sidx == NSTAGE - 1) ? 0 : sidx + 1;
    }

    const float* beg = be + (size_t)e * HDIM + n0;
    const int cl = (lane & 3) * 2;
    const int rl = lane >> 2;
#pragma unroll
    for (int mi = 0; mi < 4; mi++) {
        const int r0 = wm * 64 + mi * 16 + rl;
        const int r1 = r0 + 8;
        const bool v0 = (m0 + r0) < cnt;
        const bool v1 = (m0 + r1) < cnt;
        const int   t0 = sTok[r0], t1 = sTok[r1];
        const float g0 = sGate[r0], g1 = sGate[r1];
        float* o0 = out + (size_t)t0 * HDIM + n0;
        float* o1 = out + (size_t)t1 * HDIM + n0;
#pragma unroll
        for (int nj = 0; nj < 8; nj++) {
            const int col = wn * 64 + nj * 8 + cl;
            const float b0 = beg[col], b1 = beg[col + 1];
            if (v0)
                redv2(&o0[col], g0 * (acc[mi][nj][0] + b0), g0 * (acc[mi][nj][1] + b1));
            if (v1)
                redv2(&o1[col], g1 * (acc[mi][nj][2] + b0), g1 * (acc[mi][nj][3] + b1));
        }
    }
}

// ---------------------------------------------------------------------------
extern "C" void kernel_launch(void* const* d_in, const int* in_sizes, int n_in,
                              void* d_out, int out_size) {
    const float* x  = (const float*)d_in[0];
    const float* Wg = (const float*)d_in[1];
    const float* bg = (const float*)d_in[2];
    const float* We = (const float*)d_in[3];
    const float* be = (const float*)d_in[4];
    float* out = (float*)d_out;

    cudaFuncSetAttribute(moe_gemm_mma, cudaFuncAttributeMaxDynamicSharedMemorySize, SMEM_TOTAL);

    prep_kernel<<<NB_PREP, 256>>>(x, Wg, bg, We, out);

    dim3 grid(HDIM / BN, T_TOK / BM, NEXP);
    moe_gemm_mma<<<grid, 256, SMEM_TOTAL>>>(be, out);
}

// round 17
// speedup vs baseline: 1.0515x; 1.0515x over previous
#include <cuda_runtime.h>
#include <cuda_fp16.h>
#include <cstdint>

#define T_TOK 8192
#define HDIM  2048
#define NEXP  8

// GEMM tile config (fp16 mma.sync; B via cp.async.bulk from pre-swizzled gmem)
#define BM 128
#define BN 256
#define BKC 64
#define NCHUNK (HDIM / BKC)        // 32
#define NSTAGE 4
#define A_OFF 0                    // 16 KB (128 rows x 128B)
#define B_OFF 16384                // 32 KB (256 rows x 128B)
#define STAGE_BYTES 49152
#define SM_HDR 1024
#define SMEM_TOTAL (SM_HDR + NSTAGE * STAGE_BYTES)   // 197632
#define B_BLOCK_BYTES 32768

// merged prep block partition (convert-x fused into router blocks)
#define NB_ROUTE 1024
#define NB_TRANS 8192
#define NB_INIT  1024
#define NB_PREP  (NB_ROUTE + NB_TRANS + NB_INIT)

// ---------------- device scratch (no allocations allowed) -------------------
__device__ int    d_cnt[NEXP];
__device__ int    d_list[NEXP * T_TOK];
__device__ float  d_gatev[NEXP * T_TOK];
__device__ __half d_xh[(size_t)T_TOK * HDIM];
// We^T pre-swizzled tile layout: block[(e*8+nt)*32+c] of 32KB; inside:
// swz128(row*128 + (kk>>3)*16) + (kk&7)*2  for n=nt*256+row, k=c*64+kk
__device__ __half d_wtile[(size_t)NEXP * HDIM * HDIM];

// ---------------- helpers ---------------------------------------------------
__device__ __forceinline__ uint32_t smem_u32(const void* p) {
    uint32_t a;
    asm("{ .reg .u64 t; cvta.to.shared.u64 t, %1; cvt.u32.u64 %0, t; }" : "=r"(a) : "l"(p));
    return a;
}
__device__ __forceinline__ uint32_t swz128(uint32_t o) { return o ^ ((o >> 3) & 0x70); }
__device__ __forceinline__ void cp16(uint32_t dst, const void* src) {
    asm volatile("cp.async.cg.shared.global [%0], [%1], 16;" :: "r"(dst), "l"(src));
}
__device__ __forceinline__ void ldm4(uint32_t addr, uint32_t& r0, uint32_t& r1,
                                     uint32_t& r2, uint32_t& r3) {
    asm volatile("ldmatrix.sync.aligned.m8n8.x4.shared.b16 {%0,%1,%2,%3}, [%4];"
                 : "=r"(r0), "=r"(r1), "=r"(r2), "=r"(r3) : "r"(addr));
}
__device__ __forceinline__ void mma16816(float* c, const uint32_t* a,
                                         uint32_t b0, uint32_t b1) {
    asm volatile(
        "mma.sync.aligned.m16n8k16.row.col.f32.f16.f16.f32 "
        "{%0,%1,%2,%3}, {%4,%5,%6,%7}, {%8,%9}, {%0,%1,%2,%3};"
        : "+f"(c[0]), "+f"(c[1]), "+f"(c[2]), "+f"(c[3])
        : "r"(a[0]), "r"(a[1]), "r"(a[2]), "r"(a[3]), "r"(b0), "r"(b1));
}
__device__ __forceinline__ void redv2(float* addr, float a, float b) {
    asm volatile("red.global.add.v2.f32 [%0], {%1, %2};"
                 :: "l"(addr), "f"(a), "f"(b) : "memory");
}
__device__ __forceinline__ void mbar_init(uint32_t a, uint32_t cnt) {
    asm volatile("mbarrier.init.shared.b64 [%0], %1;" :: "r"(a), "r"(cnt) : "memory");
}
__device__ __forceinline__ void mbar_expect_tx(uint32_t a, uint32_t tx) {
    asm volatile("mbarrier.arrive.expect_tx.shared.b64 _, [%0], %1;"
                 :: "r"(a), "r"(tx) : "memory");
}
__device__ __forceinline__ void mbar_wait(uint32_t a, uint32_t ph) {
    asm volatile(
        "{\n\t.reg .pred P;\n\tWL_%=:\n\t"
        "mbarrier.try_wait.parity.acquire.cta.shared::cta.b64 P, [%0], %1, 0x989680;\n\t"
        "@P bra.uni WD_%=;\n\tbra.uni WL_%=;\n\tWD_%=:\n\t}"
        :: "r"(a), "r"(ph) : "memory");
}
__device__ __forceinline__ void bulk_ld(uint32_t dst, const void* src,
                                        uint32_t bytes, uint32_t mbar) {
    asm volatile("cp.async.bulk.shared::cta.global.mbarrier::complete_tx::bytes "
                 "[%0], [%1], %2, [%3];"
                 :: "r"(dst), "l"(src), "r"(bytes), "r"(mbar) : "memory");
}

// ---------------- kernel A: zero routing counters ----------------------------
__global__ void zero_cnt() {
    if (threadIdx.x < NEXP) d_cnt[threadIdx.x] = 0;
}

// ---------------- kernel B: merged prep --------------------------------------
__global__ void __launch_bounds__(256)
prep_kernel(const float* __restrict__ x, const float* __restrict__ Wg,
            const float* __restrict__ bg, const float* __restrict__ We,
            float* __restrict__ out) {
    __shared__ float tile[64][68];
    const int b = blockIdx.x;
    const int tid = threadIdx.x;

    if (b < NB_ROUTE) {
        // ---------------- router + convert (warp per token) ----------------
        const int lane = tid & 31;
        const int t = b * 8 + (tid >> 5);
        float acc[NEXP];
#pragma unroll
        for (int e = 0; e < NEXP; e++) acc[e] = 0.f;
        const float* xr = x + (size_t)t * HDIM;
#pragma unroll 4
        for (int j = 0; j < HDIM / 32; j++) {
            const int h = lane + 32 * j;
            const float xs = xr[h];
            const float4* wr = (const float4*)(Wg + (size_t)h * NEXP);
            float4 w0 = wr[0], w1 = wr[1];
            acc[0] += xs * w0.x; acc[1] += xs * w0.y; acc[2] += xs * w0.z; acc[3] += xs * w0.w;
            acc[4] += xs * w1.x; acc[5] += xs * w1.y; acc[6] += xs * w1.z; acc[7] += xs * w1.w;
        }
        {
            const float4* xr4 = (const float4*)xr;
            __half2* xh = (__half2*)(d_xh + (size_t)t * HDIM);
#pragma unroll 4
            for (int j = 0; j < 16; j++) {
                const int i4 = lane + 32 * j;
                float4 v = xr4[i4];
                xh[2 * i4]     = __floats2half2_rn(v.x, v.y);
                xh[2 * i4 + 1] = __floats2half2_rn(v.z, v.w);
            }
        }
#pragma unroll
        for (int e = 0; e < NEXP; e++) {
#pragma unroll
            for (int s = 16; s > 0; s >>= 1)
                acc[e] += __shfl_xor_sync(0xFFFFFFFFu, acc[e], s);
        }
        if (lane == 0) {
#pragma unroll
            for (int e = 0; e < NEXP; e++) acc[e] += bg[e];
            float m = acc[0];
#pragma unroll
            for (int e = 1; e < NEXP; e++) m = fmaxf(m, acc[e]);
            float p[NEXP], s = 0.f;
#pragma unroll
            for (int e = 0; e < NEXP; e++) { p[e] = __expf(acc[e] - m); s += p[e]; }
            float inv = 1.f / s;
#pragma unroll
            for (int e = 0; e < NEXP; e++) p[e] *= inv;
            int i0 = 0;
#pragma unroll
            for (int e = 1; e < NEXP; e++) if (p[e] > p[i0]) i0 = e;
            int i1 = (i0 == 0) ? 1 : 0;
#pragma unroll
            for (int e = 0; e < NEXP; e++) if (e != i0 && p[e] > p[i1]) i1 = e;
            int pos0 = atomicAdd(&d_cnt[i0], 1);
            d_list[i0 * T_TOK + pos0] = t;  d_gatev[i0 * T_TOK + pos0] = p[i0];
            int pos1 = atomicAdd(&d_cnt[i1], 1);
            d_list[i1 * T_TOK + pos1] = t;  d_gatev[i1 * T_TOK + pos1] = p[i1];
        }
    } else if (b < NB_ROUTE + NB_TRANS) {
        // ---------------- transpose+convert We (64n x 64k tile) ----------------
        const int bt = b - NB_ROUTE;
        const int e  = bt >> 10;
        const int rem = bt & 1023;
        const int n0 = (rem & 31) * 64;
        const int k0 = (rem >> 5) * 64;

        const float* src = We + ((size_t)e * HDIM + k0) * HDIM + n0;
#pragma unroll
        for (int i = 0; i < 4; i++) {
            const int idx = tid + 256 * i;
            const int r  = idx >> 4;
            const int c4 = idx & 15;
            float4 v = *(const float4*)(src + (size_t)r * HDIM + c4 * 4);
            tile[r][c4 * 4 + 0] = v.x; tile[r][c4 * 4 + 1] = v.y;
            tile[r][c4 * 4 + 2] = v.z; tile[r][c4 * 4 + 3] = v.w;
        }
        __syncthreads();

        const int nl = tid >> 2;
        const int n  = n0 + nl;
        const int nt = n >> 8;
        const int row = n & 255;
        const int c  = k0 >> 6;
        char* blk = (char*)d_wtile + (((size_t)(e * 8 + nt) * 32 + c) * B_BLOCK_BYTES);
#pragma unroll
        for (int gi = 0; gi < 2; gi++) {
            const int g  = (tid & 3) + gi * 4;
            const int kk = g * 8;
            __half h[8];
#pragma unroll
            for (int j = 0; j < 8; j++) h[j] = __float2half_rn(tile[kk + j][nl]);
            const uint32_t off = swz128((uint32_t)(row * 128 + g * 16));
            *(uint4*)(blk + off) = *(const uint4*)h;
        }
    } else {
        // ---------------- zero output ----------------
        const int bi = b - NB_ROUTE - NB_TRANS;
        const int n4 = (T_TOK * HDIM) / 4;
        float4 z = make_float4(0.f, 0.f, 0.f, 0.f);
        float4* o4 = (float4*)out;
        for (int j = bi * 256 + tid; j < n4; j += NB_INIT * 256) o4[j] = z;
    }
}

// ---------------- kernel C: grouped GEMM, 512 threads, 4x4 warp grid ---------
__global__ void __launch_bounds__(512, 1)
moe_gemm_mma(const float* __restrict__ be, float* __restrict__ out) {
    const int e = blockIdx.z;
    const int cnt = d_cnt[e];
    const int m0 = blockIdx.y * BM;
    if (m0 >= cnt) return;
    const int nt = blockIdx.x;
    const int n0 = nt * BN;

    extern __shared__ char smem[];
    const uint32_t sb = smem_u32(smem);
    const int tid  = threadIdx.x;
    const int wid  = tid >> 5;
    const int lane = tid & 31;
    const int wm   = wid >> 2;       // 0..3  (m: 32 each)
    const int wn   = wid & 3;        // 0..3  (n: 64 each)

    int*   sTok  = (int*)smem;
    float* sGate = (float*)(smem + 512);
    const uint32_t mbar0 = sb + 960;     // 4 mbarriers

    if (tid == 0) {
#pragma unroll
        for (int s = 0; s < NSTAGE; s++) mbar_init(mbar0 + 8 * s, 1);
    }
    if (tid < BM) {
        int r = m0 + tid;
        if (r < cnt) { sTok[tid] = d_list[e * T_TOK + r]; sGate[tid] = d_gatev[e * T_TOK + r]; }
        else         { sTok[tid] = 0;                      sGate[tid] = 0.f; }
    }
    asm volatile("fence.proxy.async.shared::cta;" ::: "memory");
    __syncthreads();

    // --- A gather: 4 threads/row, 2x16B each (chunks q and q+4) ---
    const int arow = tid >> 2;           // 0..127
    const int q    = tid & 3;
    uint32_t sD[2];
    sD[0] = swz128((uint32_t)(arow * 128 + q * 16));
    sD[1] = swz128((uint32_t)(arow * 128 + (q + 4) * 16));
    const __half* aS = d_xh + (size_t)sTok[arow] * HDIM + q * 8;
    const char* bBase = (const char*)d_wtile + ((size_t)(e * 8 + nt) * 32) * B_BLOCK_BYTES;

    const uint32_t stgBase = sb + SM_HDR;

#define ISSUE_CHUNK(sidx_, c_)                                                \
    {                                                                         \
        const uint32_t stg_ = stgBase + (sidx_) * STAGE_BYTES;                \
        if (tid == 0) {                                                       \
            mbar_expect_tx(mbar0 + 8 * (sidx_), B_BLOCK_BYTES);               \
            bulk_ld(stg_ + B_OFF, bBase + (size_t)(c_) * B_BLOCK_BYTES,       \
                    B_BLOCK_BYTES, mbar0 + 8 * (sidx_));                      \
        }                                                                     \
        cp16(stg_ + A_OFF + sD[0], aS + (c_) * BKC);                          \
        cp16(stg_ + A_OFF + sD[1], aS + (c_) * BKC + 32);                     \
        asm volatile("cp.async.commit_group;" ::: "memory");                  \
    }

    // --- ldmatrix addressing ---
    uint32_t aRow[2], bRow[4];
#pragma unroll
    for (int mi = 0; mi < 2; mi++) aRow[mi] = wm * 32 + mi * 16 + (lane & 15);
#pragma unroll
    for (int j = 0; j < 4; j++)    bRow[j]  = wn * 64 + j * 16 + (lane & 15);
    const uint32_t kcHalf = (lane >> 4);

    float acc[2][8][4];
#pragma unroll
    for (int mi = 0; mi < 2; mi++)
#pragma unroll
        for (int nj = 0; nj < 8; nj++)
#pragma unroll
            for (int q2 = 0; q2 < 4; q2++) acc[mi][nj][q2] = 0.f;

    ISSUE_CHUNK(0, 0);
    ISSUE_CHUNK(1, 1);
    ISSUE_CHUNK(2, 2);
    ISSUE_CHUNK(3, 3);

    int sidx = 0;
    for (int c = 0; c < NCHUNK; c++) {
        asm volatile("cp.async.wait_group 3;" ::: "memory");
        mbar_wait(mbar0 + 8 * sidx, (c / NSTAGE) & 1);
        __syncthreads();
        const uint32_t stage = stgBase + sidx * STAGE_BYTES;

#pragma unroll
        for (int ks = 0; ks < 4; ks++) {
            const uint32_t kc = ks * 2 + kcHalf;
            uint32_t a[2][4];
#pragma unroll
            for (int mi = 0; mi < 2; mi++) {
                uint32_t off = aRow[mi] * 128 + ((kc ^ (aRow[mi] & 7)) << 4);
                ldm4(stage + A_OFF + off, a[mi][0], a[mi][1], a[mi][2], a[mi][3]);
            }
            uint32_t bfr[4][4];
#pragma unroll
            for (int j = 0; j < 4; j++) {
                uint32_t off = bRow[j] * 128 + ((kc ^ (bRow[j] & 7)) << 4);
                ldm4(stage + B_OFF + off, bfr[j][0], bfr[j][1], bfr[j][2], bfr[j][3]);
            }
#pragma unroll
            for (int mi = 0; mi < 2; mi++) {
#pragma unroll
                for (int nj = 0; nj < 8; nj++) {
                    const int j = nj >> 1, h = nj & 1;
                    mma16816(acc[mi][nj], a[mi], bfr[j][h], bfr[j][h + 2]);
                }
            }
        }

        __syncthreads();
        if (c + NSTAGE < NCHUNK) {
            ISSUE_CHUNK(sidx, c + NSTAGE);
        } else {
            asm volatile("cp.async.commit_group;" ::: "memory");
        }
        sidx = (sidx == NSTAGE - 1) ? 0 : sidx + 1;
    }

    const float* beg = be + (size_t)e * HDIM + n0;
    const int cl = (lane & 3) * 2;
    const int rl = lane >> 2;
#pragma unroll
    for (int mi = 0; mi < 2; mi++) {
        const int r0 = wm * 32 + mi * 16 + rl;
        const int r1 = r0 + 8;
        const bool v0 = (m0 + r0) < cnt;
        const bool v1 = (m0 + r1) < cnt;
        const int   t0 = sTok[r0], t1 = sTok[r1];
        const float g0 = sGate[r0], g1 = sGate[r1];
        float* o0 = out + (size_t)t0 * HDIM + n0;
        float* o1 = out + (size_t)t1 * HDIM + n0;
#pragma unroll
        for (int nj = 0; nj < 8; nj++) {
            const int col = wn * 64 + nj * 8 + cl;
            const float b0 = beg[col], b1 = beg[col + 1];
            if (v0)
                redv2(&o0[col], g0 * (acc[mi][nj][0] + b0), g0 * (acc[mi][nj][1] + b1));
            if (v1)
                redv2(&o1[col], g1 * (acc[mi][nj][2] + b0), g1 * (acc[mi][nj][3] + b1));
        }
    }
}

// ---------------------------------------------------------------------------
extern "C" void kernel_launch(void* const* d_in, const int* in_sizes, int n_in,
                              void* d_out, int out_size) {
    const float* x  = (const float*)d_in[0];
    const float* Wg = (const float*)d_in[1];
    const float* bg = (const float*)d_in[2];
    const float* We = (const float*)d_in[3];
    const float* be = (const float*)d_in[4];
    float* out = (float*)d_out;

    cudaFuncSetAttribute(moe_gemm_mma, cudaFuncAttributeMaxDynamicSharedMemorySize, SMEM_TOTAL);

    zero_cnt<<<1, 32>>>();
    prep_kernel<<<NB_PREP, 256>>>(x, Wg, bg, We, out);

    dim3 grid(HDIM / BN, T_TOK / BM, NEXP);
    moe_gemm_mma<<<grid, 512, SMEM_TOTAL>>>(be, out);
}